// round 15
// baseline (speedup 1.0000x reference)
#include <cuda_runtime.h>
#include <cuda_bf16.h>
#include <math.h>
#include <stdint.h>

#define NDIM  4096
#define BDIM  512
#define EPSV  1.0f
#define LAMDA 10.0f

// ---------------- scratch (static device globals; no allocation) -------------
__device__ __nv_bfloat16 g_Kb [NDIM * NDIM];   // K bf16 [m][k] (only copy of K)
__device__ __nv_bfloat16 g_fT [BDIM * NDIM];   // f^T bf16 [n][k]
__device__ __nv_bfloat16 g_aTb[BDIM * NDIM];   // a^T bf16 [n][k]
__device__ float g_C  [NDIM * BDIM];           // Kf      [4096][512]
__device__ float g_KTa[NDIM * BDIM];           // K^T @ a [4096][512]
__device__ float g_acc[4];                     // S1, S2, S3, S4

// ---------------- helpers -----------------------------------------------------
__device__ __forceinline__ uint32_t smem_u32(const void* p) {
    return (uint32_t)__cvta_generic_to_shared(p);
}
__device__ __forceinline__ void cpasync16(uint32_t dst, const void* src) {
    asm volatile("cp.async.cg.shared.global [%0], [%1], 16;"
                 :: "r"(dst), "l"(src) : "memory");
}
__device__ __forceinline__ void mma_bf16(float* c, const uint32_t* a, const uint32_t* b) {
    asm volatile(
        "mma.sync.aligned.m16n8k16.row.col.f32.bf16.bf16.f32 "
        "{%0,%1,%2,%3}, {%4,%5,%6,%7}, {%8,%9}, {%0,%1,%2,%3};"
        : "+f"(c[0]), "+f"(c[1]), "+f"(c[2]), "+f"(c[3])
        : "r"(a[0]), "r"(a[1]), "r"(a[2]), "r"(a[3]), "r"(b[0]), "r"(b[1]));
}
__device__ __forceinline__ void ldsm4(uint32_t& r0, uint32_t& r1, uint32_t& r2,
                                      uint32_t& r3, uint32_t addr) {
    asm volatile("ldmatrix.sync.aligned.m8n8.x4.shared.b16 {%0,%1,%2,%3}, [%4];"
                 : "=r"(r0), "=r"(r1), "=r"(r2), "=r"(r3) : "r"(addr));
}
__device__ __forceinline__ void ldsm4t(uint32_t& r0, uint32_t& r1, uint32_t& r2,
                                       uint32_t& r3, uint32_t addr) {
    asm volatile("ldmatrix.sync.aligned.m8n8.x4.trans.shared.b16 {%0,%1,%2,%3}, [%4];"
                 : "=r"(r0), "=r"(r1), "=r"(r2), "=r"(r3) : "r"(addr));
}

// Fast ln on the FMA pipe: exponent extraction (mantissa in [2/3, 4/3)) +
// degree-9 Taylor (truncation <= (1/3)^10/10 ~ 1.7e-6 abs). Zero MUFU ops.
__device__ __forceinline__ float fast_logf(float v) {
    int   i = __float_as_int(v);
    int   e = (i - 0x3f2aaaab) >> 23;            // m in [2/3, 4/3)
    float x = __int_as_float(i - (e << 23)) - 1.0f;   // x in [-1/3, 1/3)
    float q = fmaf(x, 0.111111111f, -0.125f);
    q = fmaf(x, q, 0.142857143f);
    q = fmaf(x, q, -0.166666667f);
    q = fmaf(x, q, 0.2f);
    q = fmaf(x, q, -0.25f);
    q = fmaf(x, q, 0.333333333f);
    q = fmaf(x, q, -0.5f);
    q = fmaf(x, q, 1.0f);
    return fmaf((float)e, 0.693147181f, x * q);
}

// f = (10/(10-u))^10 via one rcp + squaring chain; flog = 10*ln(r) via poly.
__device__ __forceinline__ void f_and_flog(float u, float& f, float& flog) {
    float r  = __fdividef(LAMDA, LAMDA - u);     // 1 MUFU
    flog = LAMDA * fast_logf(r);
    float r2 = r * r, r4 = r2 * r2, r8 = r4 * r4;
    f = r8 * r2;
}

// ---------------- bf16 tensor-core GEMM (split-K, atomic accumulate) -----------
#define STAGES 3
#define BKT 32

template <bool TRANSA>
__global__ void __launch_bounds__(256, 2)
gemm_bf16(const __nv_bfloat16* __restrict__ A, const __nv_bfloat16* __restrict__ B,
          float* __restrict__ C, int ncols, int ktiles)
{
    extern __shared__ uint32_t sm32[];
    constexpr int A_TSZ32 = TRANSA ? (32 * 68) : (128 * 20);
    constexpr int B_TSZ32 = 128 * 20;
    constexpr int STG32   = A_TSZ32 + B_TSZ32;

    const int tid  = threadIdx.x;
    const int wid  = tid >> 5, lane = tid & 31;
    const int grp  = lane >> 2, tg = lane & 3;
    const int wm   = (wid >> 2) * 64;
    const int wn   = (wid & 3) * 32;
    const int bm   = blockIdx.y * 128;
    const int bn   = blockIdx.x * 128;
    const int kt0  = blockIdx.z * ktiles;

    const int a_row = (lane & 15);
    const int a_kc  = (lane >> 4);
    const int ta_k  = (lane >> 4) * 8 + (lane & 7);
    const int ta_m  = ((lane >> 3) & 1) * 8;
    const int b_row = (lane & 7) + ((lane >> 4) & 1) * 8;
    const int b_kc  = ((lane >> 3) & 1);

    float acc[4][4][4];
#pragma unroll
    for (int i = 0; i < 4; i++)
#pragma unroll
        for (int j = 0; j < 4; j++)
#pragma unroll
            for (int k = 0; k < 4; k++) acc[i][j][k] = 0.0f;

    auto load_stage = [&](int kt, int s) {
        uint32_t* As = sm32 + s * STG32;
        uint32_t* Bs = As + A_TSZ32;
        const int k0 = (kt0 + kt) * BKT;
        if (!TRANSA) {
#pragma unroll
            for (int h = 0; h < 2; h++) {
                int ch = tid + h * 256;
                int r = ch >> 2, c = ch & 3;
                cpasync16(smem_u32(As + r * 20 + c * 4),
                          A + (size_t)(bm + r) * 4096 + k0 + c * 8);
            }
        } else {
#pragma unroll
            for (int h = 0; h < 2; h++) {
                int ch = tid + h * 256;
                int r = ch >> 4, c = ch & 15;
                cpasync16(smem_u32(As + r * 68 + c * 4),
                          A + (size_t)(k0 + r) * 4096 + bm + c * 8);
            }
        }
#pragma unroll
        for (int h = 0; h < 2; h++) {
            int ch = tid + h * 256;
            int r = ch >> 2, c = ch & 3;
            cpasync16(smem_u32(Bs + r * 20 + c * 4),
                      B + (size_t)(bn + r) * 4096 + k0 + c * 8);
        }
        asm volatile("cp.async.commit_group;" ::: "memory");
    };

    for (int kt = 0; kt < STAGES - 1; kt++) load_stage(kt, kt);

    for (int kt = 0; kt < ktiles; kt++) {
        asm volatile("cp.async.wait_group %0;" :: "n"(STAGES - 2) : "memory");
        __syncthreads();

        int nx = kt + STAGES - 1;
        if (nx < ktiles) load_stage(nx, nx % STAGES);

        const uint32_t Asb = smem_u32(sm32 + (kt % STAGES) * STG32);
        const uint32_t Bsb = Asb + A_TSZ32 * 4;

#pragma unroll
        for (int ks = 0; ks < 2; ks++) {
            uint32_t af[4][4], bf[4][2];
#pragma unroll
            for (int mf = 0; mf < 4; mf++) {
                if (!TRANSA) {
                    uint32_t addr = Asb + (uint32_t)(wm + mf * 16 + a_row) * 80u
                                  + (uint32_t)(ks * 2 + a_kc) * 16u;
                    ldsm4(af[mf][0], af[mf][1], af[mf][2], af[mf][3], addr);
                } else {
                    uint32_t addr = Asb + (uint32_t)(ks * 16 + ta_k) * 272u
                                  + (uint32_t)(wm + mf * 16 + ta_m) * 2u;
                    ldsm4t(af[mf][0], af[mf][1], af[mf][2], af[mf][3], addr);
                }
            }
#pragma unroll
            for (int np = 0; np < 2; np++) {
                uint32_t addr = Bsb + (uint32_t)(wn + np * 16 + b_row) * 80u
                              + (uint32_t)(ks * 2 + b_kc) * 16u;
                ldsm4(bf[2 * np][0], bf[2 * np][1],
                      bf[2 * np + 1][0], bf[2 * np + 1][1], addr);
            }
#pragma unroll
            for (int mf = 0; mf < 4; mf++)
#pragma unroll
                for (int nf = 0; nf < 4; nf++)
                    mma_bf16(acc[mf][nf], af[mf], bf[nf]);
        }
    }

#pragma unroll
    for (int mf = 0; mf < 4; mf++)
#pragma unroll
        for (int nf = 0; nf < 4; nf++) {
            int row = bm + wm + mf * 16 + grp;
            int col = bn + wn + nf * 8 + 2 * tg;
            float* c0 = C + (size_t)row * ncols + col;
            float* c1 = C + (size_t)(row + 8) * ncols + col;
            atomicAdd(c0,     acc[mf][nf][0]);
            atomicAdd(c0 + 1, acc[mf][nf][1]);
            atomicAdd(c1,     acc[mf][nf][2]);
            atomicAdd(c1 + 1, acc[mf][nf][3]);
        }
}

// ---------------- kprep: K -> bf16 (streaming convert) -------------------------
__global__ void __launch_bounds__(256) kprep_kernel(const float4* __restrict__ K) {
    size_t i = (size_t)blockIdx.x * 512 + threadIdx.x * 2;
    float4 v0 = K[i], v1 = K[i + 1];
    __nv_bfloat16 o[8] = {
        __float2bfloat16(v0.x), __float2bfloat16(v0.y),
        __float2bfloat16(v0.z), __float2bfloat16(v0.w),
        __float2bfloat16(v1.x), __float2bfloat16(v1.y),
        __float2bfloat16(v1.z), __float2bfloat16(v1.w)};
    *reinterpret_cast<float4*>(g_Kb + i * 4) = *reinterpret_cast<float4*>(o);
}

// ---------------- prep: f^T bf16 from U (rcp + squaring, no log/exp) -----------
__global__ void __launch_bounds__(1024) prep_kernel(const float* __restrict__ U) {
    __shared__ float fs[32][33];
    int tx = threadIdx.x, ty = threadIdx.y;
    int i0 = blockIdx.x * 32, j0 = blockIdx.y * 32;
    float u  = U[(size_t)(i0 + ty) * BDIM + j0 + tx];
    float r  = __fdividef(LAMDA, LAMDA - u);
    float r2 = r * r, r4 = r2 * r2, r8 = r4 * r4;
    fs[ty][tx] = r8 * r2;
    __syncthreads();
    g_fT[(size_t)(j0 + ty) * NDIM + i0 + tx] = __float2bfloat16(fs[tx][ty]);
}

// ---------------- reductions ---------------------------------------------------
__device__ __forceinline__ float warp_sum(float v) {
#pragma unroll
    for (int o = 16; o > 0; o >>= 1) v += __shfl_down_sync(0xffffffffu, v, o);
    return v;
}

// ---------------- epilogue 1: a^T bf16, S2/S3 -> g_acc -------------------------
__global__ void __launch_bounds__(1024) epi1_kernel(const float* __restrict__ P) {
    __shared__ float as[32][33];
    __shared__ float sh2[32], sh3[32];
    int tx = threadIdx.x, ty = threadIdx.y;
    int j0 = blockIdx.x * 32, i0 = blockIdx.y * 32;
    int i = i0 + ty, j = j0 + tx;

    float kf = g_C[(size_t)i * BDIM + j];
    float p  = P[(size_t)i * BDIM + j];
    float a  = __fdividef(p, kf);               // 1 MUFU
    as[ty][tx] = a;

    float s2 = p * fast_logf(a);                // poly log: FMA pipe
    float s3 = p;

    int lt = ty * 32 + tx, lane = lt & 31, w = lt >> 5;
    s2 = warp_sum(s2); s3 = warp_sum(s3);
    if (lane == 0) { sh2[w] = s2; sh3[w] = s3; }
    __syncthreads();

    g_aTb[(size_t)(j0 + ty) * NDIM + i0 + tx] = __float2bfloat16(as[tx][ty]);

    if (w == 0) {
        float v2 = sh2[lane], v3 = sh3[lane];
        v2 = warp_sum(v2); v3 = warp_sum(v3);
        if (lane == 0) { atomicAdd(&g_acc[1], v2); atomicAdd(&g_acc[2], v3); }
    }
}

// ---------------- epilogue 2: S1/S4 -> g_acc -----------------------------------
__global__ void __launch_bounds__(512) epi2_kernel(const float* __restrict__ U) {
    __shared__ float sh1[16], sh4[16];
    int i = blockIdx.x, j = threadIdx.x;
    float kta = g_KTa[(size_t)i * BDIM + j];
    float u   = U[(size_t)i * BDIM + j];
    float f, flog;
    f_and_flog(u, f, flog);                     // 1 MUFU total
    float fk = f * kta;
    float s1 = fk * flog;
    float s4 = fk * (EPSV * flog + LAMDA);

    s1 = warp_sum(s1); s4 = warp_sum(s4);
    int lane = j & 31, w = j >> 5;
    if (lane == 0) { sh1[w] = s1; sh4[w] = s4; }
    __syncthreads();
    if (w == 0) {
        float v1 = (lane < 16) ? sh1[lane] : 0.0f;
        float v4 = (lane < 16) ? sh4[lane] : 0.0f;
        v1 = warp_sum(v1); v4 = warp_sum(v4);
        if (lane == 0) { atomicAdd(&g_acc[0], v1); atomicAdd(&g_acc[3], v4); }
    }
}

// ---------------- final combine ------------------------------------------------
__global__ void final_kernel(float* __restrict__ out) {
    out[0] = EPSV * (g_acc[0] + g_acc[1] - g_acc[2]) - g_acc[3];
}

// ---------------- launch -------------------------------------------------------
extern "C" void kernel_launch(void* const* d_in, const int* in_sizes, int n_in,
                              void* d_out, int out_size) {
    const float* U = (const float*)d_in[0];
    const float* P = (const float*)d_in[1];
    const float* K = (const float*)d_in[2];
    float* out = (float*)d_out;

    __nv_bfloat16 *pKb, *pfT, *paTb;
    float *pC, *pKTa, *pAcc;
    cudaGetSymbolAddress((void**)&pKb,  g_Kb);
    cudaGetSymbolAddress((void**)&pfT,  g_fT);
    cudaGetSymbolAddress((void**)&paTb, g_aTb);
    cudaGetSymbolAddress((void**)&pC,   g_C);
    cudaGetSymbolAddress((void**)&pKTa, g_KTa);
    cudaGetSymbolAddress((void**)&pAcc, g_acc);

    constexpr int SMEM_N = STAGES * (128 * 20 + 128 * 20) * 4;  // 61440 B
    constexpr int SMEM_T = STAGES * (32 * 68 + 128 * 20) * 4;   // 56832 B
    cudaFuncSetAttribute((const void*)gemm_bf16<false>,
                         cudaFuncAttributeMaxDynamicSharedMemorySize, SMEM_N);
    cudaFuncSetAttribute((const void*)gemm_bf16<true>,
                         cudaFuncAttributeMaxDynamicSharedMemorySize, SMEM_T);
    cudaFuncSetAttribute((const void*)gemm_bf16<false>,
                         cudaFuncAttributePreferredSharedMemoryCarveout, 100);
    cudaFuncSetAttribute((const void*)gemm_bf16<true>,
                         cudaFuncAttributePreferredSharedMemoryCarveout, 100);

    dim3 t32(32, 32);

    // 0) zero split-K accumulators + scalar sums
    cudaMemsetAsync(pC,   0, (size_t)NDIM * BDIM * sizeof(float), 0);
    cudaMemsetAsync(pKTa, 0, (size_t)NDIM * BDIM * sizeof(float), 0);
    cudaMemsetAsync(pAcc, 0, 4 * sizeof(float), 0);

    // 1) K -> bf16; f^T bf16
    kprep_kernel<<<NDIM * NDIM / 2048, 256>>>((const float4*)K);
    prep_kernel<<<dim3(NDIM / 32, BDIM / 32), t32>>>(U);

    // 2) Kf = Kb @ fT^T            (split-K=2 -> 256 CTAs)
    gemm_bf16<false><<<dim3(BDIM / 128, NDIM / 128, 2), 256, SMEM_N>>>(
        pKb, pfT, pC, BDIM, 4096 / BKT / 2);

    // 3) a = P/Kf -> a^T bf16 + S2,S3
    epi1_kernel<<<dim3(BDIM / 32, NDIM / 32), t32>>>(P);

    // 4) K^T @ a = Kb^T @ aTb^T    (trans-A ldmatrix; split-K=2 -> 256 CTAs)
    gemm_bf16<true><<<dim3(BDIM / 128, NDIM / 128, 2), 256, SMEM_T>>>(
        pKb, paTb, pKTa, BDIM, 4096 / BKT / 2);

    // 5) S1, S4
    epi2_kernel<<<NDIM, 512>>>(U);

    // 6) combine
    final_kernel<<<1, 1>>>(out);
}

// round 16
// speedup vs baseline: 1.1280x; 1.1280x over previous
#include <cuda_runtime.h>
#include <cuda_bf16.h>
#include <math.h>
#include <stdint.h>

#define NDIM  4096
#define BDIM  512
#define EPSV  1.0f
#define LAMDA 10.0f

// ---------------- scratch (static device globals; no allocation) -------------
__device__ __nv_bfloat16 g_Kb [NDIM * NDIM];   // K bf16 [m][k] (only copy of K)
__device__ __nv_bfloat16 g_fT [BDIM * NDIM];   // f^T bf16 [n][k]
__device__ __nv_bfloat16 g_aTb[BDIM * NDIM];   // a^T bf16 [n][k]
__device__ float g_C  [NDIM * BDIM];           // Kf [4096][512]
__device__ float g_acc[4];                     // S1, S2, S3, S4

// ---------------- helpers -----------------------------------------------------
__device__ __forceinline__ uint32_t smem_u32(const void* p) {
    return (uint32_t)__cvta_generic_to_shared(p);
}
__device__ __forceinline__ void cpasync16(uint32_t dst, const void* src) {
    asm volatile("cp.async.cg.shared.global [%0], [%1], 16;"
                 :: "r"(dst), "l"(src) : "memory");
}
__device__ __forceinline__ void mma_bf16(float* c, const uint32_t* a, const uint32_t* b) {
    asm volatile(
        "mma.sync.aligned.m16n8k16.row.col.f32.bf16.bf16.f32 "
        "{%0,%1,%2,%3}, {%4,%5,%6,%7}, {%8,%9}, {%0,%1,%2,%3};"
        : "+f"(c[0]), "+f"(c[1]), "+f"(c[2]), "+f"(c[3])
        : "r"(a[0]), "r"(a[1]), "r"(a[2]), "r"(a[3]), "r"(b[0]), "r"(b[1]));
}
__device__ __forceinline__ void ldsm4(uint32_t& r0, uint32_t& r1, uint32_t& r2,
                                      uint32_t& r3, uint32_t addr) {
    asm volatile("ldmatrix.sync.aligned.m8n8.x4.shared.b16 {%0,%1,%2,%3}, [%4];"
                 : "=r"(r0), "=r"(r1), "=r"(r2), "=r"(r3) : "r"(addr));
}
__device__ __forceinline__ void ldsm4t(uint32_t& r0, uint32_t& r1, uint32_t& r2,
                                       uint32_t& r3, uint32_t addr) {
    asm volatile("ldmatrix.sync.aligned.m8n8.x4.trans.shared.b16 {%0,%1,%2,%3}, [%4];"
                 : "=r"(r0), "=r"(r1), "=r"(r2), "=r"(r3) : "r"(addr));
}

// Fast ln on the FMA pipe (deg-9 Taylor after exponent extraction; <=1.7e-6 abs)
__device__ __forceinline__ float fast_logf(float v) {
    int   i = __float_as_int(v);
    int   e = (i - 0x3f2aaaab) >> 23;                 // m in [2/3, 4/3)
    float x = __int_as_float(i - (e << 23)) - 1.0f;   // x in [-1/3, 1/3)
    float q = fmaf(x, 0.111111111f, -0.125f);
    q = fmaf(x, q, 0.142857143f);
    q = fmaf(x, q, -0.166666667f);
    q = fmaf(x, q, 0.2f);
    q = fmaf(x, q, -0.25f);
    q = fmaf(x, q, 0.333333333f);
    q = fmaf(x, q, -0.5f);
    q = fmaf(x, q, 1.0f);
    return fmaf((float)e, 0.693147181f, x * q);
}

// f = (10/(10-u))^10 via rcp + squaring; flog = 10*ln(r) via poly.
__device__ __forceinline__ void f_and_flog(float u, float& f, float& flog) {
    float r  = __fdividef(LAMDA, LAMDA - u);
    flog = LAMDA * fast_logf(r);
    float r2 = r * r, r4 = r2 * r2, r8 = r4 * r4;
    f = r8 * r2;
}

// ---------------- bf16 tensor-core GEMM (split-K) ------------------------------
// FUSE=false: C += op(A) @ B^T via atomicAdd (GEMM1: Kf).
// FUSE=true : no C output; epilogue computes S1 += f*flog*kta, S4 += f*(flog+L)*kta
//             from U at each (row,col) -- linear in kta so split-K partials sum.
#define STAGES 3
#define BKT 32

template <bool TRANSA, bool FUSE>
__global__ void __launch_bounds__(256, 2)
gemm_bf16(const __nv_bfloat16* __restrict__ A, const __nv_bfloat16* __restrict__ B,
          float* __restrict__ C, const float* __restrict__ U, int ncols, int ktiles)
{
    extern __shared__ uint32_t sm32[];
    constexpr int A_TSZ32 = TRANSA ? (32 * 68) : (128 * 20);
    constexpr int B_TSZ32 = 128 * 20;
    constexpr int STG32   = A_TSZ32 + B_TSZ32;

    const int tid  = threadIdx.x;
    const int wid  = tid >> 5, lane = tid & 31;
    const int grp  = lane >> 2, tg = lane & 3;
    const int wm   = (wid >> 2) * 64;
    const int wn   = (wid & 3) * 32;
    const int bm   = blockIdx.y * 128;
    const int bn   = blockIdx.x * 128;
    const int kt0  = blockIdx.z * ktiles;

    const int a_row = (lane & 15);
    const int a_kc  = (lane >> 4);
    const int ta_k  = (lane >> 4) * 8 + (lane & 7);
    const int ta_m  = ((lane >> 3) & 1) * 8;
    const int b_row = (lane & 7) + ((lane >> 4) & 1) * 8;
    const int b_kc  = ((lane >> 3) & 1);

    float acc[4][4][4];
#pragma unroll
    for (int i = 0; i < 4; i++)
#pragma unroll
        for (int j = 0; j < 4; j++)
#pragma unroll
            for (int k = 0; k < 4; k++) acc[i][j][k] = 0.0f;

    auto load_stage = [&](int kt, int s) {
        uint32_t* As = sm32 + s * STG32;
        uint32_t* Bs = As + A_TSZ32;
        const int k0 = (kt0 + kt) * BKT;
        if (!TRANSA) {
#pragma unroll
            for (int h = 0; h < 2; h++) {
                int ch = tid + h * 256;
                int r = ch >> 2, c = ch & 3;
                cpasync16(smem_u32(As + r * 20 + c * 4),
                          A + (size_t)(bm + r) * 4096 + k0 + c * 8);
            }
        } else {
#pragma unroll
            for (int h = 0; h < 2; h++) {
                int ch = tid + h * 256;
                int r = ch >> 4, c = ch & 15;
                cpasync16(smem_u32(As + r * 68 + c * 4),
                          A + (size_t)(k0 + r) * 4096 + bm + c * 8);
            }
        }
#pragma unroll
        for (int h = 0; h < 2; h++) {
            int ch = tid + h * 256;
            int r = ch >> 2, c = ch & 3;
            cpasync16(smem_u32(Bs + r * 20 + c * 4),
                      B + (size_t)(bn + r) * 4096 + k0 + c * 8);
        }
        asm volatile("cp.async.commit_group;" ::: "memory");
    };

    for (int kt = 0; kt < STAGES - 1; kt++) load_stage(kt, kt);

    for (int kt = 0; kt < ktiles; kt++) {
        asm volatile("cp.async.wait_group %0;" :: "n"(STAGES - 2) : "memory");
        __syncthreads();

        int nx = kt + STAGES - 1;
        if (nx < ktiles) load_stage(nx, nx % STAGES);

        const uint32_t Asb = smem_u32(sm32 + (kt % STAGES) * STG32);
        const uint32_t Bsb = Asb + A_TSZ32 * 4;

#pragma unroll
        for (int ks = 0; ks < 2; ks++) {
            uint32_t af[4][4], bf[4][2];
#pragma unroll
            for (int mf = 0; mf < 4; mf++) {
                if (!TRANSA) {
                    uint32_t addr = Asb + (uint32_t)(wm + mf * 16 + a_row) * 80u
                                  + (uint32_t)(ks * 2 + a_kc) * 16u;
                    ldsm4(af[mf][0], af[mf][1], af[mf][2], af[mf][3], addr);
                } else {
                    uint32_t addr = Asb + (uint32_t)(ks * 16 + ta_k) * 272u
                                  + (uint32_t)(wm + mf * 16 + ta_m) * 2u;
                    ldsm4t(af[mf][0], af[mf][1], af[mf][2], af[mf][3], addr);
                }
            }
#pragma unroll
            for (int np = 0; np < 2; np++) {
                uint32_t addr = Bsb + (uint32_t)(wn + np * 16 + b_row) * 80u
                              + (uint32_t)(ks * 2 + b_kc) * 16u;
                ldsm4(bf[2 * np][0], bf[2 * np][1],
                      bf[2 * np + 1][0], bf[2 * np + 1][1], addr);
            }
#pragma unroll
            for (int mf = 0; mf < 4; mf++)
#pragma unroll
                for (int nf = 0; nf < 4; nf++)
                    mma_bf16(acc[mf][nf], af[mf], bf[nf]);
        }
    }

    if (!FUSE) {
#pragma unroll
        for (int mf = 0; mf < 4; mf++)
#pragma unroll
            for (int nf = 0; nf < 4; nf++) {
                int row = bm + wm + mf * 16 + grp;
                int col = bn + wn + nf * 8 + 2 * tg;
                float* c0 = C + (size_t)row * ncols + col;
                float* c1 = C + (size_t)(row + 8) * ncols + col;
                atomicAdd(c0,     acc[mf][nf][0]);
                atomicAdd(c0 + 1, acc[mf][nf][1]);
                atomicAdd(c1,     acc[mf][nf][2]);
                atomicAdd(c1 + 1, acc[mf][nf][3]);
            }
    } else {
        float s1 = 0.0f, s4 = 0.0f;
#pragma unroll
        for (int mf = 0; mf < 4; mf++)
#pragma unroll
            for (int nf = 0; nf < 4; nf++) {
                int row = bm + wm + mf * 16 + grp;
                int col = bn + wn + nf * 8 + 2 * tg;
                float2 u0 = *reinterpret_cast<const float2*>(U + (size_t)row * BDIM + col);
                float2 u1 = *reinterpret_cast<const float2*>(U + (size_t)(row + 8) * BDIM + col);
                float f, fl;
                f_and_flog(u0.x, f, fl);
                s1 = fmaf(f * fl, acc[mf][nf][0], s1);
                s4 = fmaf(f * (fl + LAMDA), acc[mf][nf][0], s4);
                f_and_flog(u0.y, f, fl);
                s1 = fmaf(f * fl, acc[mf][nf][1], s1);
                s4 = fmaf(f * (fl + LAMDA), acc[mf][nf][1], s4);
                f_and_flog(u1.x, f, fl);
                s1 = fmaf(f * fl, acc[mf][nf][2], s1);
                s4 = fmaf(f * (fl + LAMDA), acc[mf][nf][2], s4);
                f_and_flog(u1.y, f, fl);
                s1 = fmaf(f * fl, acc[mf][nf][3], s1);
                s4 = fmaf(f * (fl + LAMDA), acc[mf][nf][3], s4);
            }
        // block reduction -> 2 atomics
#pragma unroll
        for (int o = 16; o > 0; o >>= 1) {
            s1 += __shfl_down_sync(0xffffffffu, s1, o);
            s4 += __shfl_down_sync(0xffffffffu, s4, o);
        }
        __syncthreads();                       // mainloop smem reads done
        float* red = (float*)sm32;
        if (lane == 0) { red[wid] = s1; red[8 + wid] = s4; }
        __syncthreads();
        if (tid == 0) {
            float t1 = 0, t4 = 0;
#pragma unroll
            for (int w = 0; w < 8; w++) { t1 += red[w]; t4 += red[8 + w]; }
            atomicAdd(&g_acc[0], t1);
            atomicAdd(&g_acc[3], t4);
        }
    }
}

// ---------------- kprep: K -> bf16 (streaming convert) -------------------------
__global__ void __launch_bounds__(256) kprep_kernel(const float4* __restrict__ K) {
    size_t i = (size_t)blockIdx.x * 512 + threadIdx.x * 2;
    float4 v0 = K[i], v1 = K[i + 1];
    __nv_bfloat16 o[8] = {
        __float2bfloat16(v0.x), __float2bfloat16(v0.y),
        __float2bfloat16(v0.z), __float2bfloat16(v0.w),
        __float2bfloat16(v1.x), __float2bfloat16(v1.y),
        __float2bfloat16(v1.z), __float2bfloat16(v1.w)};
    *reinterpret_cast<float4*>(g_Kb + i * 4) = *reinterpret_cast<float4*>(o);
}

// ---------------- prep: f^T bf16 from U (256 thr, 4 rows/thread) ---------------
__global__ void __launch_bounds__(256) prep_kernel(const float* __restrict__ U) {
    __shared__ float fs[32][33];
    int tx = threadIdx.x, ty = threadIdx.y;        // (32, 8)
    int i0 = blockIdx.x * 32, j0 = blockIdx.y * 32;
#pragma unroll
    for (int q = 0; q < 4; q++) {
        int r = ty + q * 8;
        float u  = U[(size_t)(i0 + r) * BDIM + j0 + tx];
        float rc = __fdividef(LAMDA, LAMDA - u);
        float r2 = rc * rc, r4 = r2 * r2, r8 = r4 * r4;
        fs[r][tx] = r8 * r2;
    }
    __syncthreads();
#pragma unroll
    for (int q = 0; q < 4; q++) {
        int r = ty + q * 8;
        g_fT[(size_t)(j0 + r) * NDIM + i0 + tx] = __float2bfloat16(fs[tx][r]);
    }
}

// ---------------- reductions ---------------------------------------------------
__device__ __forceinline__ float warp_sum(float v) {
#pragma unroll
    for (int o = 16; o > 0; o >>= 1) v += __shfl_down_sync(0xffffffffu, v, o);
    return v;
}

// ---------------- epilogue 1: a^T bf16, S2/S3 (256 thr, 4 elems/thread) --------
__global__ void __launch_bounds__(256) epi1_kernel(const float* __restrict__ P) {
    __shared__ float as[32][33];
    __shared__ float red[16];
    int tx = threadIdx.x, ty = threadIdx.y;        // (32, 8)
    int j0 = blockIdx.x * 32, i0 = blockIdx.y * 32;
    float s2 = 0.0f, s3 = 0.0f;
#pragma unroll
    for (int q = 0; q < 4; q++) {
        int r = ty + q * 8;
        int i = i0 + r, j = j0 + tx;
        float kf = g_C[(size_t)i * BDIM + j];
        float p  = P [(size_t)i * BDIM + j];
        float a  = __fdividef(p, kf);
        as[r][tx] = a;
        s2 += p * fast_logf(a);
        s3 += p;
    }
    __syncthreads();
#pragma unroll
    for (int q = 0; q < 4; q++) {
        int r = ty + q * 8;
        g_aTb[(size_t)(j0 + r) * NDIM + i0 + tx] = __float2bfloat16(as[tx][r]);
    }
    int lt = ty * 32 + tx, lane = lt & 31, w = lt >> 5;
    s2 = warp_sum(s2); s3 = warp_sum(s3);
    if (lane == 0) { red[w] = s2; red[8 + w] = s3; }
    __syncthreads();
    if (lt == 0) {
        float v2 = 0, v3 = 0;
#pragma unroll
        for (int k = 0; k < 8; k++) { v2 += red[k]; v3 += red[8 + k]; }
        atomicAdd(&g_acc[1], v2);
        atomicAdd(&g_acc[2], v3);
    }
}

// ---------------- final combine ------------------------------------------------
__global__ void final_kernel(float* __restrict__ out) {
    out[0] = EPSV * (g_acc[0] + g_acc[1] - g_acc[2]) - g_acc[3];
}

// ---------------- launch -------------------------------------------------------
extern "C" void kernel_launch(void* const* d_in, const int* in_sizes, int n_in,
                              void* d_out, int out_size) {
    const float* U = (const float*)d_in[0];
    const float* P = (const float*)d_in[1];
    const float* K = (const float*)d_in[2];
    float* out = (float*)d_out;

    __nv_bfloat16 *pKb, *pfT, *paTb;
    float *pC, *pAcc;
    cudaGetSymbolAddress((void**)&pKb,  g_Kb);
    cudaGetSymbolAddress((void**)&pfT,  g_fT);
    cudaGetSymbolAddress((void**)&paTb, g_aTb);
    cudaGetSymbolAddress((void**)&pC,   g_C);
    cudaGetSymbolAddress((void**)&pAcc, g_acc);

    constexpr int SMEM_N = STAGES * (128 * 20 + 128 * 20) * 4;  // 61440 B
    constexpr int SMEM_T = STAGES * (32 * 68 + 128 * 20) * 4;   // 56832 B
    cudaFuncSetAttribute((const void*)gemm_bf16<false, false>,
                         cudaFuncAttributeMaxDynamicSharedMemorySize, SMEM_N);
    cudaFuncSetAttribute((const void*)gemm_bf16<true, true>,
                         cudaFuncAttributeMaxDynamicSharedMemorySize, SMEM_T);
    cudaFuncSetAttribute((const void*)gemm_bf16<false, false>,
                         cudaFuncAttributePreferredSharedMemoryCarveout, 100);
    cudaFuncSetAttribute((const void*)gemm_bf16<true, true>,
                         cudaFuncAttributePreferredSharedMemoryCarveout, 100);

    dim3 t328(32, 8);

    // 0) zero GEMM1 accumulator + scalar sums
    cudaMemsetAsync(pC,   0, (size_t)NDIM * BDIM * sizeof(float), 0);
    cudaMemsetAsync(pAcc, 0, 4 * sizeof(float), 0);

    // 1) K -> bf16; f^T bf16
    kprep_kernel<<<NDIM * NDIM / 2048, 256>>>((const float4*)K);
    prep_kernel<<<dim3(NDIM / 32, BDIM / 32), t328>>>(U);

    // 2) Kf = Kb @ fT^T            (split-K=2 -> 256 CTAs)
    gemm_bf16<false, false><<<dim3(BDIM / 128, NDIM / 128, 2), 256, SMEM_N>>>(
        pKb, pfT, pC, nullptr, BDIM, 4096 / BKT / 2);

    // 3) a = P/Kf -> a^T bf16 + S2,S3
    epi1_kernel<<<dim3(BDIM / 32, NDIM / 32), t328>>>(P);

    // 4) K^T @ a with fused S1/S4 epilogue (split-K=2 -> 256 CTAs; no KTa output)
    gemm_bf16<true, true><<<dim3(BDIM / 128, NDIM / 128, 2), 256, SMEM_T>>>(
        pKb, paTb, nullptr, U, BDIM, 4096 / BKT / 2);

    // 5) combine
    final_kernel<<<1, 1>>>(out);
}

// round 17
// speedup vs baseline: 1.1611x; 1.0293x over previous
#include <cuda_runtime.h>
#include <cuda_bf16.h>
#include <math.h>
#include <stdint.h>

#define NDIM  4096
#define BDIM  512
#define EPSV  1.0f
#define LAMDA 10.0f

// ---------------- scratch (static device globals; no allocation) -------------
__device__ __nv_bfloat16 g_Kb [NDIM * NDIM];   // K bf16 [m][k] (only copy of K)
__device__ __nv_bfloat16 g_fT [BDIM * NDIM];   // f^T bf16 [n][k]
__device__ __nv_bfloat16 g_aTb[BDIM * NDIM];   // a^T bf16 [n][k]
__device__ float g_acc[4];                     // S1, S2, S3, S4

// ---------------- helpers -----------------------------------------------------
__device__ __forceinline__ uint32_t smem_u32(const void* p) {
    return (uint32_t)__cvta_generic_to_shared(p);
}
__device__ __forceinline__ void cpasync16(uint32_t dst, const void* src) {
    asm volatile("cp.async.cg.shared.global [%0], [%1], 16;"
                 :: "r"(dst), "l"(src) : "memory");
}
__device__ __forceinline__ void mma_bf16(float* c, const uint32_t* a, const uint32_t* b) {
    asm volatile(
        "mma.sync.aligned.m16n8k16.row.col.f32.bf16.bf16.f32 "
        "{%0,%1,%2,%3}, {%4,%5,%6,%7}, {%8,%9}, {%0,%1,%2,%3};"
        : "+f"(c[0]), "+f"(c[1]), "+f"(c[2]), "+f"(c[3])
        : "r"(a[0]), "r"(a[1]), "r"(a[2]), "r"(a[3]), "r"(b[0]), "r"(b[1]));
}
__device__ __forceinline__ void ldsm4(uint32_t& r0, uint32_t& r1, uint32_t& r2,
                                      uint32_t& r3, uint32_t addr) {
    asm volatile("ldmatrix.sync.aligned.m8n8.x4.shared.b16 {%0,%1,%2,%3}, [%4];"
                 : "=r"(r0), "=r"(r1), "=r"(r2), "=r"(r3) : "r"(addr));
}
__device__ __forceinline__ void ldsm4t(uint32_t& r0, uint32_t& r1, uint32_t& r2,
                                       uint32_t& r3, uint32_t addr) {
    asm volatile("ldmatrix.sync.aligned.m8n8.x4.trans.shared.b16 {%0,%1,%2,%3}, [%4];"
                 : "=r"(r0), "=r"(r1), "=r"(r2), "=r"(r3) : "r"(addr));
}

// Fast ln on the FMA pipe (deg-9 Taylor after exponent extraction; <=1.7e-6 abs)
__device__ __forceinline__ float fast_logf(float v) {
    int   i = __float_as_int(v);
    int   e = (i - 0x3f2aaaab) >> 23;                 // m in [2/3, 4/3)
    float x = __int_as_float(i - (e << 23)) - 1.0f;   // x in [-1/3, 1/3)
    float q = fmaf(x, 0.111111111f, -0.125f);
    q = fmaf(x, q, 0.142857143f);
    q = fmaf(x, q, -0.166666667f);
    q = fmaf(x, q, 0.2f);
    q = fmaf(x, q, -0.25f);
    q = fmaf(x, q, 0.333333333f);
    q = fmaf(x, q, -0.5f);
    q = fmaf(x, q, 1.0f);
    return fmaf((float)e, 0.693147181f, x * q);
}

// f = (10/(10-u))^10 via rcp + squaring; flog = 10*ln(r) via poly.
__device__ __forceinline__ void f_and_flog(float u, float& f, float& flog) {
    float r  = __fdividef(LAMDA, LAMDA - u);
    flog = LAMDA * fast_logf(r);
    float r2 = r * r, r4 = r2 * r2, r8 = r4 * r4;
    f = r8 * r2;
}

// ---------------- bf16 tensor-core GEMM ---------------------------------------
// MODE 1 (GEMM1, unsplit): acc = full Kf tile. Epilogue: a = P/Kf, S2/S3 atomics,
//         a^T bf16 written via smem transpose (coalesced).  AUX = P.
// MODE 2 (GEMM2, split-K): S1 += f*flog*kta, S4 += f*(flog+L)*kta per element;
//         linear in kta so split partials sum.  AUX = U.
#define STAGES 3
#define BKT 32

template <bool TRANSA, int MODE>
__global__ void __launch_bounds__(256, 2)
gemm_bf16(const __nv_bfloat16* __restrict__ A, const __nv_bfloat16* __restrict__ B,
          const float* __restrict__ AUX, int ktiles)
{
    extern __shared__ uint32_t sm32[];
    constexpr int A_TSZ32 = TRANSA ? (32 * 68) : (128 * 20);
    constexpr int B_TSZ32 = 128 * 20;
    constexpr int STG32   = A_TSZ32 + B_TSZ32;

    const int tid  = threadIdx.x;
    const int wid  = tid >> 5, lane = tid & 31;
    const int grp  = lane >> 2, tg = lane & 3;
    const int wm   = (wid >> 2) * 64;
    const int wn   = (wid & 3) * 32;
    const int bm   = blockIdx.y * 128;
    const int bn   = blockIdx.x * 128;
    const int kt0  = blockIdx.z * ktiles;

    const int a_row = (lane & 15);
    const int a_kc  = (lane >> 4);
    const int ta_k  = (lane >> 4) * 8 + (lane & 7);
    const int ta_m  = ((lane >> 3) & 1) * 8;
    const int b_row = (lane & 7) + ((lane >> 4) & 1) * 8;
    const int b_kc  = ((lane >> 3) & 1);

    float acc[4][4][4];
#pragma unroll
    for (int i = 0; i < 4; i++)
#pragma unroll
        for (int j = 0; j < 4; j++)
#pragma unroll
            for (int k = 0; k < 4; k++) acc[i][j][k] = 0.0f;

    auto load_stage = [&](int kt, int s) {
        uint32_t* As = sm32 + s * STG32;
        uint32_t* Bs = As + A_TSZ32;
        const int k0 = (kt0 + kt) * BKT;
        if (!TRANSA) {
#pragma unroll
            for (int h = 0; h < 2; h++) {
                int ch = tid + h * 256;
                int r = ch >> 2, c = ch & 3;
                cpasync16(smem_u32(As + r * 20 + c * 4),
                          A + (size_t)(bm + r) * 4096 + k0 + c * 8);
            }
        } else {
#pragma unroll
            for (int h = 0; h < 2; h++) {
                int ch = tid + h * 256;
                int r = ch >> 4, c = ch & 15;
                cpasync16(smem_u32(As + r * 68 + c * 4),
                          A + (size_t)(k0 + r) * 4096 + bm + c * 8);
            }
        }
#pragma unroll
        for (int h = 0; h < 2; h++) {
            int ch = tid + h * 256;
            int r = ch >> 2, c = ch & 3;
            cpasync16(smem_u32(Bs + r * 20 + c * 4),
                      B + (size_t)(bn + r) * 4096 + k0 + c * 8);
        }
        asm volatile("cp.async.commit_group;" ::: "memory");
    };

    for (int kt = 0; kt < STAGES - 1; kt++) load_stage(kt, kt);

    for (int kt = 0; kt < ktiles; kt++) {
        asm volatile("cp.async.wait_group %0;" :: "n"(STAGES - 2) : "memory");
        __syncthreads();

        int nx = kt + STAGES - 1;
        if (nx < ktiles) load_stage(nx, nx % STAGES);

        const uint32_t Asb = smem_u32(sm32 + (kt % STAGES) * STG32);
        const uint32_t Bsb = Asb + A_TSZ32 * 4;

#pragma unroll
        for (int ks = 0; ks < 2; ks++) {
            uint32_t af[4][4], bf[4][2];
#pragma unroll
            for (int mf = 0; mf < 4; mf++) {
                if (!TRANSA) {
                    uint32_t addr = Asb + (uint32_t)(wm + mf * 16 + a_row) * 80u
                                  + (uint32_t)(ks * 2 + a_kc) * 16u;
                    ldsm4(af[mf][0], af[mf][1], af[mf][2], af[mf][3], addr);
                } else {
                    uint32_t addr = Asb + (uint32_t)(ks * 16 + ta_k) * 272u
                                  + (uint32_t)(wm + mf * 16 + ta_m) * 2u;
                    ldsm4t(af[mf][0], af[mf][1], af[mf][2], af[mf][3], addr);
                }
            }
#pragma unroll
            for (int np = 0; np < 2; np++) {
                uint32_t addr = Bsb + (uint32_t)(wn + np * 16 + b_row) * 80u
                              + (uint32_t)(ks * 2 + b_kc) * 16u;
                ldsm4(bf[2 * np][0], bf[2 * np][1],
                      bf[2 * np + 1][0], bf[2 * np + 1][1], addr);
            }
#pragma unroll
            for (int mf = 0; mf < 4; mf++)
#pragma unroll
                for (int nf = 0; nf < 4; nf++)
                    mma_bf16(acc[mf][nf], af[mf], bf[nf]);
        }
    }

    if (MODE == 1) {
        // acc holds the COMPLETE Kf tile (unsplit). AUX = P.
        __syncthreads();                         // mainloop smem reads done
        __nv_bfloat16* at = (__nv_bfloat16*)sm32;   // [128 n][stride 136] bf16
        float s2 = 0.0f, s3 = 0.0f;
#pragma unroll
        for (int mf = 0; mf < 4; mf++)
#pragma unroll
            for (int nf = 0; nf < 4; nf++) {
                int rl = wm + mf * 16 + grp;     // local m
                int cl = wn + nf * 8 + 2 * tg;   // local n
                int row = bm + rl, colg = bn + cl;
                float2 p0 = *reinterpret_cast<const float2*>(AUX + (size_t)row * BDIM + colg);
                float2 p1 = *reinterpret_cast<const float2*>(AUX + (size_t)(row + 8) * BDIM + colg);
                float a0 = __fdividef(p0.x, acc[mf][nf][0]);
                float a1 = __fdividef(p0.y, acc[mf][nf][1]);
                float a2 = __fdividef(p1.x, acc[mf][nf][2]);
                float a3 = __fdividef(p1.y, acc[mf][nf][3]);
                s2 += p0.x * fast_logf(a0) + p0.y * fast_logf(a1)
                    + p1.x * fast_logf(a2) + p1.y * fast_logf(a3);
                s3 += p0.x + p0.y + p1.x + p1.y;
                at[(size_t)cl * 136 + rl]           = __float2bfloat16(a0);
                at[(size_t)(cl + 1) * 136 + rl]     = __float2bfloat16(a1);
                at[(size_t)cl * 136 + rl + 8]       = __float2bfloat16(a2);
                at[(size_t)(cl + 1) * 136 + rl + 8] = __float2bfloat16(a3);
            }
        __syncthreads();
        // coalesced a^T store: 128 n-rows x 128 bf16 = 8192 u32
#pragma unroll
        for (int h = 0; h < 32; h++) {
            int idx = tid + h * 256;
            int rn = idx >> 6, c = idx & 63;
            uint32_t v = *reinterpret_cast<uint32_t*>((char*)at + rn * 272 + c * 4);
            *reinterpret_cast<uint32_t*>(
                (char*)g_aTb + ((size_t)(bn + rn) * 4096 + bm) * 2 + c * 4) = v;
        }
        // reduce S2, S3
#pragma unroll
        for (int o = 16; o > 0; o >>= 1) {
            s2 += __shfl_down_sync(0xffffffffu, s2, o);
            s3 += __shfl_down_sync(0xffffffffu, s3, o);
        }
        float* red = (float*)(sm32 + 8704);      // past the 34816B at-tile
        __syncthreads();
        if (lane == 0) { red[wid] = s2; red[8 + wid] = s3; }
        __syncthreads();
        if (tid == 0) {
            float t2 = 0, t3 = 0;
#pragma unroll
            for (int w = 0; w < 8; w++) { t2 += red[w]; t3 += red[8 + w]; }
            atomicAdd(&g_acc[1], t2);
            atomicAdd(&g_acc[2], t3);
        }
    } else {
        // MODE 2: AUX = U; S1/S4 from split-K partial kta (linear in kta)
        float s1 = 0.0f, s4 = 0.0f;
#pragma unroll
        for (int mf = 0; mf < 4; mf++)
#pragma unroll
            for (int nf = 0; nf < 4; nf++) {
                int row = bm + wm + mf * 16 + grp;
                int col = bn + wn + nf * 8 + 2 * tg;
                float2 u0 = *reinterpret_cast<const float2*>(AUX + (size_t)row * BDIM + col);
                float2 u1 = *reinterpret_cast<const float2*>(AUX + (size_t)(row + 8) * BDIM + col);
                float f, fl;
                f_and_flog(u0.x, f, fl);
                s1 = fmaf(f * fl, acc[mf][nf][0], s1);
                s4 = fmaf(f * (fl + LAMDA), acc[mf][nf][0], s4);
                f_and_flog(u0.y, f, fl);
                s1 = fmaf(f * fl, acc[mf][nf][1], s1);
                s4 = fmaf(f * (fl + LAMDA), acc[mf][nf][1], s4);
                f_and_flog(u1.x, f, fl);
                s1 = fmaf(f * fl, acc[mf][nf][2], s1);
                s4 = fmaf(f * (fl + LAMDA), acc[mf][nf][2], s4);
                f_and_flog(u1.y, f, fl);
                s1 = fmaf(f * fl, acc[mf][nf][3], s1);
                s4 = fmaf(f * (fl + LAMDA), acc[mf][nf][3], s4);
            }
#pragma unroll
        for (int o = 16; o > 0; o >>= 1) {
            s1 += __shfl_down_sync(0xffffffffu, s1, o);
            s4 += __shfl_down_sync(0xffffffffu, s4, o);
        }
        __syncthreads();
        float* red = (float*)sm32;
        if (lane == 0) { red[wid] = s1; red[8 + wid] = s4; }
        __syncthreads();
        if (tid == 0) {
            float t1 = 0, t4 = 0;
#pragma unroll
            for (int w = 0; w < 8; w++) { t1 += red[w]; t4 += red[8 + w]; }
            atomicAdd(&g_acc[0], t1);
            atomicAdd(&g_acc[3], t4);
        }
    }
}

// ---------------- kprep: K -> bf16 (streaming convert) -------------------------
__global__ void __launch_bounds__(256) kprep_kernel(const float4* __restrict__ K) {
    size_t i = (size_t)blockIdx.x * 512 + threadIdx.x * 2;
    float4 v0 = K[i], v1 = K[i + 1];
    __nv_bfloat16 o[8] = {
        __float2bfloat16(v0.x), __float2bfloat16(v0.y),
        __float2bfloat16(v0.z), __float2bfloat16(v0.w),
        __float2bfloat16(v1.x), __float2bfloat16(v1.y),
        __float2bfloat16(v1.z), __float2bfloat16(v1.w)};
    *reinterpret_cast<float4*>(g_Kb + i * 4) = *reinterpret_cast<float4*>(o);
}

// ---------------- prep: f^T bf16 from U (256 thr, 4 rows/thread) ---------------
__global__ void __launch_bounds__(256) prep_kernel(const float* __restrict__ U) {
    __shared__ float fs[32][33];
    int tx = threadIdx.x, ty = threadIdx.y;        // (32, 8)
    int i0 = blockIdx.x * 32, j0 = blockIdx.y * 32;
#pragma unroll
    for (int q = 0; q < 4; q++) {
        int r = ty + q * 8;
        float u  = U[(size_t)(i0 + r) * BDIM + j0 + tx];
        float rc = __fdividef(LAMDA, LAMDA - u);
        float r2 = rc * rc, r4 = r2 * r2, r8 = r4 * r4;
        fs[r][tx] = r8 * r2;
    }
    __syncthreads();
#pragma unroll
    for (int q = 0; q < 4; q++) {
        int r = ty + q * 8;
        g_fT[(size_t)(j0 + r) * NDIM + i0 + tx] = __float2bfloat16(fs[tx][r]);
    }
}

// ---------------- final combine ------------------------------------------------
__global__ void final_kernel(float* __restrict__ out) {
    out[0] = EPSV * (g_acc[0] + g_acc[1] - g_acc[2]) - g_acc[3];
}

// ---------------- launch -------------------------------------------------------
extern "C" void kernel_launch(void* const* d_in, const int* in_sizes, int n_in,
                              void* d_out, int out_size) {
    const float* U = (const float*)d_in[0];
    const float* P = (const float*)d_in[1];
    const float* K = (const float*)d_in[2];
    float* out = (float*)d_out;

    __nv_bfloat16 *pKb, *pfT, *paTb;
    float* pAcc;
    cudaGetSymbolAddress((void**)&pKb,  g_Kb);
    cudaGetSymbolAddress((void**)&pfT,  g_fT);
    cudaGetSymbolAddress((void**)&paTb, g_aTb);
    cudaGetSymbolAddress((void**)&pAcc, g_acc);

    constexpr int SMEM_N = STAGES * (128 * 20 + 128 * 20) * 4;  // 61440 B
    constexpr int SMEM_T = STAGES * (32 * 68 + 128 * 20) * 4;   // 56832 B
    cudaFuncSetAttribute((const void*)gemm_bf16<false, 1>,
                         cudaFuncAttributeMaxDynamicSharedMemorySize, SMEM_N);
    cudaFuncSetAttribute((const void*)gemm_bf16<true, 2>,
                         cudaFuncAttributeMaxDynamicSharedMemorySize, SMEM_T);
    cudaFuncSetAttribute((const void*)gemm_bf16<false, 1>,
                         cudaFuncAttributePreferredSharedMemoryCarveout, 100);
    cudaFuncSetAttribute((const void*)gemm_bf16<true, 2>,
                         cudaFuncAttributePreferredSharedMemoryCarveout, 100);

    dim3 t328(32, 8);

    // 0) zero scalar sums
    cudaMemsetAsync(pAcc, 0, 4 * sizeof(float), 0);

    // 1) K -> bf16; f^T bf16
    kprep_kernel<<<NDIM * NDIM / 2048, 256>>>((const float4*)K);
    prep_kernel<<<dim3(NDIM / 32, BDIM / 32), t328>>>(U);

    // 2) Kf = Kb @ fT^T, UNSPLIT, fused epilogue: a^T bf16 + S2/S3 (128 CTAs)
    gemm_bf16<false, 1><<<dim3(BDIM / 128, NDIM / 128, 1), 256, SMEM_N>>>(
        pKb, pfT, P, 4096 / BKT);

    // 3) K^T @ a with fused S1/S4 epilogue (split-K=2 -> 256 CTAs)
    gemm_bf16<true, 2><<<dim3(BDIM / 128, NDIM / 128, 2), 256, SMEM_T>>>(
        pKb, paTb, U, 4096 / BKT / 2);

    // 4) combine
    final_kernel<<<1, 1>>>(out);
}